// round 15
// baseline (speedup 1.0000x reference)
#include <cuda_runtime.h>
#include <cuda_fp16.h>
#include <math.h>

// ============================================================================
// CrossAttention: B=4, C=256, N=4096, DK=32.
//   K1: QKV projection on f16 tensor cores (f32 accum), f16 scratch out.
//   K2: flash attention, 128-query CTAs, 512 threads / 16 warps
//       (8 row-groups x 2 ch-halves; warp = 16 rows x 128 ch), 4 warps/SMSP
//       for latency hiding. f32-D S-GEMM, f16-D PV-GEMM, f16x2 exp (exp
//       output IS the PV A-fragment), cp.async double-buffered K/V.
// ============================================================================

#define DEV_INLINE __device__ __forceinline__

constexpr int B    = 4;
constexpr int C    = 256;
constexpr int N    = 4096;
constexpr int DK   = 32;
constexpr int DTOT = 320;                       // 32 q + 32 k + 256 v (f16)
constexpr float SCALE = 0.17677669529663687f;   // 1/sqrt(32)
constexpr float KS = SCALE * 1.4426950408889634f;   // fold into exp2

// f16 scratch: (B, N, 320) = 10.5 MB
__device__ __half g_qkv[(size_t)B * N * DTOT];

// ----------------------------------------------------------------------------
// mma / ldmatrix / cp.async helpers
// ----------------------------------------------------------------------------
DEV_INLINE void mma_s(float* d, const unsigned* a, unsigned b0, unsigned b1) {
    asm("mma.sync.aligned.m16n8k16.row.col.f32.f16.f16.f32 "
        "{%0,%1,%2,%3}, {%4,%5,%6,%7}, {%8,%9}, {%0,%1,%2,%3};"
        : "+f"(d[0]), "+f"(d[1]), "+f"(d[2]), "+f"(d[3])
        : "r"(a[0]), "r"(a[1]), "r"(a[2]), "r"(a[3]), "r"(b0), "r"(b1));
}

DEV_INLINE void mma_h(unsigned* d, const unsigned* a, unsigned b0, unsigned b1) {
    asm("mma.sync.aligned.m16n8k16.row.col.f16.f16.f16.f16 "
        "{%0,%1}, {%2,%3,%4,%5}, {%6,%7}, {%0,%1};"
        : "+r"(d[0]), "+r"(d[1])
        : "r"(a[0]), "r"(a[1]), "r"(a[2]), "r"(a[3]), "r"(b0), "r"(b1));
}

DEV_INLINE void ldx4(unsigned* r, unsigned saddr) {
    asm volatile("ldmatrix.sync.aligned.m8n8.x4.shared.b16 {%0,%1,%2,%3}, [%4];"
                 : "=r"(r[0]), "=r"(r[1]), "=r"(r[2]), "=r"(r[3]) : "r"(saddr));
}

DEV_INLINE void ldx4t(unsigned* r, unsigned saddr) {
    asm volatile("ldmatrix.sync.aligned.m8n8.x4.trans.shared.b16 {%0,%1,%2,%3}, [%4];"
                 : "=r"(r[0]), "=r"(r[1]), "=r"(r[2]), "=r"(r[3]) : "r"(saddr));
}

DEV_INLINE void cp16(unsigned sdst, const void* gsrc) {
    asm volatile("cp.async.cg.shared.global [%0], [%1], 16;" :: "r"(sdst), "l"(gsrc));
}
DEV_INLINE void cp_commit() { asm volatile("cp.async.commit_group;"); }
DEV_INLINE void cp_wait1()  { asm volatile("cp.async.wait_group 1;"); }
DEV_INLINE void cp_wait0()  { asm volatile("cp.async.wait_group 0;"); }

DEV_INLINE float ex2f(float x) {
    float y;
    asm("ex2.approx.ftz.f32 %0, %1;" : "=f"(y) : "f"(x));
    return y;
}
DEV_INLINE unsigned h2ex2(unsigned a) {
    unsigned d;
    asm("ex2.approx.f16x2 %0, %1;" : "=r"(d) : "r"(a));
    return d;
}

DEV_INLINE unsigned pack_h2(float lo, float hi) {
    __half2 h = __floats2half2_rn(lo, hi);
    return *reinterpret_cast<unsigned*>(&h);
}
DEV_INLINE unsigned hmul2u(unsigned a, unsigned s) {
    __half2 r = __hmul2(*reinterpret_cast<__half2*>(&a),
                        *reinterpret_cast<__half2*>(&s));
    return *reinterpret_cast<unsigned*>(&r);
}
DEV_INLINE unsigned hadd2u(unsigned a, unsigned b) {
    __half2 r = __hadd2(*reinterpret_cast<__half2*>(&a),
                        *reinterpret_cast<__half2*>(&b));
    return *reinterpret_cast<unsigned*>(&r);
}

DEV_INLINE float get_bias(int d, const float* bq, const float* bk, const float* bv) {
    return (d < DK) ? bq[d] : (d < 2 * DK) ? bk[d - DK] : bv[d - 2 * DK];
}

// ----------------------------------------------------------------------------
// Kernel 1: projection on tensor cores (unchanged).
// ----------------------------------------------------------------------------
__global__ __launch_bounds__(256) void proj_kernel(
    const float* __restrict__ x,
    const float* __restrict__ Wq, const float* __restrict__ bq,
    const float* __restrict__ Wk, const float* __restrict__ bk,
    const float* __restrict__ Wv, const float* __restrict__ bv)
{
    __shared__ __half xs[32][72];
    __shared__ __half ws[320][40];

    const int tid  = threadIdx.x;
    const int lane = tid & 31;
    const int warp = tid >> 5;
    const int wr   = warp & 3;
    const int dh   = (warp >> 2) * 160;
    const int n0   = blockIdx.x * 64;
    const int b    = blockIdx.y;

    const unsigned sx = (unsigned)__cvta_generic_to_shared(xs);
    const unsigned sw = (unsigned)__cvta_generic_to_shared(ws);

    const int lrow  = ((lane >> 3) & 1) * 8 + (lane & 7);
    const int lcol8 = (lane >> 4) * 8;
    const int trow  = ((lane >> 4) & 1) * 8 + (lane & 7);
    const int tcol  = ((lane >> 3) & 1) * 8;

    float acc[20][4];
    #pragma unroll
    for (int j = 0; j < 20; j++)
        #pragma unroll
        for (int i = 0; i < 4; i++) acc[j][i] = 0.f;

    for (int c0 = 0; c0 < C; c0 += 32) {
        #pragma unroll
        for (int rep = 0; rep < 2; rep++) {
            int i  = tid + rep * 256;
            int c  = i >> 4;
            int n4 = (i & 15) * 4;
            float4 v = *reinterpret_cast<const float4*>(
                &x[(size_t)(b * C + c0 + c) * N + n0 + n4]);
            __half2 h0 = __floats2half2_rn(v.x, v.y);
            __half2 h1 = __floats2half2_rn(v.z, v.w);
            uint2 st;
            st.x = *reinterpret_cast<unsigned*>(&h0);
            st.y = *reinterpret_cast<unsigned*>(&h1);
            *reinterpret_cast<uint2*>(&xs[c][n4]) = st;
        }
        #pragma unroll
        for (int rep = 0; rep < 10; rep++) {
            int i  = tid + rep * 256;
            int d  = i >> 3;
            int c4 = (i & 7) * 4;
            const float* src;
            if (d < DK)            src = Wq + (size_t)d * C;
            else if (d < 2 * DK)   src = Wk + (size_t)(d - DK) * C;
            else                   src = Wv + (size_t)(d - 2 * DK) * C;
            float4 v = *reinterpret_cast<const float4*>(&src[c0 + c4]);
            __half2 h0 = __floats2half2_rn(v.x, v.y);
            __half2 h1 = __floats2half2_rn(v.z, v.w);
            uint2 st;
            st.x = *reinterpret_cast<unsigned*>(&h0);
            st.y = *reinterpret_cast<unsigned*>(&h1);
            *reinterpret_cast<uint2*>(&ws[d][c4]) = st;
        }
        __syncthreads();

        #pragma unroll
        for (int kk = 0; kk < 32; kk += 16) {
            unsigned a[4];
            ldx4t(a, sx + ((kk + trow) * 72 + 16 * wr + tcol) * 2);
            #pragma unroll
            for (int j2 = 0; j2 < 10; j2++) {
                unsigned w[4];
                ldx4(w, sw + ((dh + 16 * j2 + lrow) * 40 + kk + lcol8) * 2);
                mma_s(acc[2 * j2],     a, w[0], w[2]);
                mma_s(acc[2 * j2 + 1], a, w[1], w[3]);
            }
        }
        __syncthreads();
    }

    const int r  = lane >> 2;
    const int q2 = 2 * (lane & 3);
    const size_t rowA = ((size_t)b * N + n0 + 16 * wr + r) * DTOT;
    const size_t rowB = rowA + 8 * (size_t)DTOT;
    #pragma unroll
    for (int j = 0; j < 20; j++) {
        int d = dh + 8 * j + q2;
        float b0 = get_bias(d, bq, bk, bv);
        float b1 = get_bias(d + 1, bq, bk, bv);
        __half2 va = __floats2half2_rn(acc[j][0] + b0, acc[j][1] + b1);
        __half2 vb = __floats2half2_rn(acc[j][2] + b0, acc[j][3] + b1);
        *reinterpret_cast<__half2*>(&g_qkv[rowA + d]) = va;
        *reinterpret_cast<__half2*>(&g_qkv[rowB + d]) = vb;
    }
}

// ----------------------------------------------------------------------------
// Kernel 2: flash attention, 128-query CTAs, 512 threads / 16 warps.
//   warp w: rgrp = w&7 (16-row block), h = w>>3 (128-ch half).
// smem: sQ[128][40], sK[2][64][40], sV[2][64][264] (f16) -> 88064 B
// ----------------------------------------------------------------------------
constexpr int SQ_OFF  = 0;                     // 128*40*2 = 10240
constexpr int SK_OFF  = 10240;
constexpr int SK_SZ   = 5120;                  // 64*40*2
constexpr int SV_OFF  = SK_OFF + 2 * SK_SZ;    // 20480
constexpr int SV_SZ   = 64 * 264 * 2;          // 33792
constexpr int SMEM_BYTES = SV_OFF + 2 * SV_SZ; // 88064

__global__ __launch_bounds__(512) void flash_kernel(
    const float* __restrict__ x, float* __restrict__ out)
{
    extern __shared__ char smem[];
    const unsigned sbase = (unsigned)__cvta_generic_to_shared(smem);

    const int tid  = threadIdx.x;
    const int lane = tid & 31;
    const int warp = tid >> 5;
    const int rgrp = warp & 7;      // 16-row query group
    const int h    = warp >> 3;     // channel half (128 ch)
    const int qrow0 = 16 * rgrp;
    const int b    = blockIdx.y;
    const int m0   = blockIdx.x * 128;
    const size_t base = (size_t)b * N;

    const int lrow  = ((lane >> 3) & 1) * 8 + (lane & 7);
    const int lcol8 = (lane >> 4) * 8;

    // ---- prologue: cp.async K/V tile 0 into buf 0 ----
    {
        if (tid < 256) {               // K: 256 x 16B chunks
            int m = tid >> 2, part = tid & 3;
            cp16(sbase + SK_OFF + (m * 40 + part * 8) * 2,
                 &g_qkv[(base + m) * DTOT + DK + part * 8]);
        }
        #pragma unroll
        for (int i = 0; i < 4; i++) {  // V: 2048 x 16B chunks
            int idx = tid + i * 512;
            int m = idx >> 5, part = idx & 31;
            cp16(sbase + SV_OFF + (m * 264 + part * 8) * 2,
                 &g_qkv[(base + m) * DTOT + 2 * DK + part * 8]);
        }
        cp_commit();
    }

    // ---- load Q tile: 128 rows x 32 f16 (512 x 16B chunks, one each) ----
    {
        int m = tid >> 2, part = tid & 3;
        uint4 v = *reinterpret_cast<const uint4*>(
            &g_qkv[(base + m0 + m) * DTOT + part * 8]);
        *reinterpret_cast<uint4*>(smem + SQ_OFF + (m * 40 + part * 8) * 2) = v;
    }
    __syncthreads();

    // Q fragments: 2 ksteps
    unsigned qf[2][4];
    #pragma unroll
    for (int t = 0; t < 2; t++)
        ldx4(qf[t], sbase + SQ_OFF + ((qrow0 + lrow) * 40 + 16 * t + lcol8) * 2);

    // O accumulators: 16 ch-tiles x f16x2 pair = 32 regs
    unsigned o[16][2];
    #pragma unroll
    for (int j = 0; j < 16; j++) { o[j][0] = 0u; o[j][1] = 0u; }

    float m2a = -1e30f, m2b = -1e30f;
    float La = 0.f, Lb = 0.f;

    for (int kt = 0; kt < 64; kt++) {
        const int buf = kt & 1;

        if (kt < 63) {
            const int n0t = (kt + 1) * 64;
            const unsigned skd = sbase + SK_OFF + (buf ^ 1) * SK_SZ;
            const unsigned svd = sbase + SV_OFF + (buf ^ 1) * SV_SZ;
            if (tid < 256) {
                int m = tid >> 2, part = tid & 3;
                cp16(skd + (m * 40 + part * 8) * 2,
                     &g_qkv[(base + n0t + m) * DTOT + DK + part * 8]);
            }
            #pragma unroll
            for (int i = 0; i < 4; i++) {
                int idx = tid + i * 512;
                int m = idx >> 5, part = idx & 31;
                cp16(svd + (m * 264 + part * 8) * 2,
                     &g_qkv[(base + n0t + m) * DTOT + 2 * DK + part * 8]);
            }
            cp_commit();
            cp_wait1();
        } else {
            cp_wait0();
        }
        __syncthreads();

        const unsigned skb = sbase + SK_OFF + buf * SK_SZ;
        const unsigned svb = sbase + SV_OFF + buf * SV_SZ;

        // ---- S = Q K^T (f32 accum): 8 n-tiles x 2 ksteps ----
        float sacc[8][4];
        #pragma unroll
        for (int j = 0; j < 8; j++)
            #pragma unroll
            for (int i = 0; i < 4; i++) sacc[j][i] = 0.f;

        #pragma unroll
        for (int j2 = 0; j2 < 4; j2++) {
            unsigned k0[4], k1[4];
            ldx4(k0, skb + ((16 * j2 + lrow) * 40 + 0  + lcol8) * 2);
            ldx4(k1, skb + ((16 * j2 + lrow) * 40 + 16 + lcol8) * 2);
            mma_s(sacc[2 * j2],     qf[0], k0[0], k0[2]);
            mma_s(sacc[2 * j2],     qf[1], k1[0], k1[2]);
            mma_s(sacc[2 * j2 + 1], qf[0], k0[1], k0[3]);
            mma_s(sacc[2 * j2 + 1], qf[1], k1[1], k1[3]);
        }

        // ---- online softmax (f32 max, f16x2 exp) ----
        float tma = -1e30f, tmb = -1e30f;
        #pragma unroll
        for (int j = 0; j < 8; j++) {
            tma = fmaxf(tma, fmaxf(sacc[j][0], sacc[j][1]));
            tmb = fmaxf(tmb, fmaxf(sacc[j][2], sacc[j][3]));
        }
        tma = fmaxf(tma, __shfl_xor_sync(0xffffffffu, tma, 1));
        tma = fmaxf(tma, __shfl_xor_sync(0xffffffffu, tma, 2));
        tmb = fmaxf(tmb, __shfl_xor_sync(0xffffffffu, tmb, 1));
        tmb = fmaxf(tmb, __shfl_xor_sync(0xffffffffu, tmb, 2));

        float mna = fmaxf(m2a, KS * tma);
        float mnb = fmaxf(m2b, KS * tmb);
        float alpha_a = ex2f(m2a - mna);
        float alpha_b = ex2f(m2b - mnb);
        m2a = mna; m2b = mnb;

        unsigned ha2 = pack_h2(alpha_a, alpha_a);
        unsigned hb2 = pack_h2(alpha_b, alpha_b);
        #pragma unroll
        for (int j = 0; j < 16; j++) {
            o[j][0] = hmul2u(o[j][0], ha2);
            o[j][1] = hmul2u(o[j][1], hb2);
        }

        // p = ex2(KS*s - m) as f16x2; result IS the PV A-fragment
        unsigned pha[8], phb[8];
        #pragma unroll
        for (int j = 0; j < 8; j++) {
            float a0 = fmaf(KS, sacc[j][0], -mna);
            float a1 = fmaf(KS, sacc[j][1], -mna);
            float b0 = fmaf(KS, sacc[j][2], -mnb);
            float b1 = fmaf(KS, sacc[j][3], -mnb);
            pha[j] = h2ex2(pack_h2(a0, a1));
            phb[j] = h2ex2(pack_h2(b0, b1));
        }

        // row-sum via half2 tree (8 terms <= 1 each), f32 finish
        unsigned saA = hadd2u(hadd2u(hadd2u(pha[0], pha[1]), hadd2u(pha[2], pha[3])),
                              hadd2u(hadd2u(pha[4], pha[5]), hadd2u(pha[6], pha[7])));
        unsigned sbB = hadd2u(hadd2u(hadd2u(phb[0], phb[1]), hadd2u(phb[2], phb[3])),
                              hadd2u(hadd2u(phb[4], phb[5]), hadd2u(phb[6], phb[7])));
        __half2 hva = *reinterpret_cast<__half2*>(&saA);
        __half2 hvb = *reinterpret_cast<__half2*>(&sbB);
        float la = __low2float(hva) + __high2float(hva);
        float lb = __low2float(hvb) + __high2float(hvb);
        la += __shfl_xor_sync(0xffffffffu, la, 1);
        la += __shfl_xor_sync(0xffffffffu, la, 2);
        lb += __shfl_xor_sync(0xffffffffu, lb, 1);
        lb += __shfl_xor_sync(0xffffffffu, lb, 2);
        La = La * alpha_a + la;
        Lb = Lb * alpha_b + lb;

        // ---- O += P V : 4 ksteps x 16 ch-tiles ----
        #pragma unroll
        for (int t = 0; t < 4; t++) {
            unsigned pa[4] = {pha[2 * t], phb[2 * t], pha[2 * t + 1], phb[2 * t + 1]};
            #pragma unroll
            for (int u = 0; u < 8; u++) {
                unsigned vf[4];
                ldx4t(vf, svb + ((16 * t + lrow) * 264 + h * 128 + 16 * u + lcol8) * 2);
                mma_h(o[2 * u],     pa, vf[0], vf[1]);
                mma_h(o[2 * u + 1], pa, vf[2], vf[3]);
            }
        }
        __syncthreads();
    }

    // ---- epilogue: normalize, transpose via smem, residual add ----
    const float inva = 1.f / La;
    const float invb = 1.f / Lb;
    const int qq = lane & 3;
    const int aa = lane >> 2;

    float* stage = reinterpret_cast<float*>(smem);   // [128 ch][132 m] fp32
    #pragma unroll
    for (int ph = 0; ph < 2; ph++) {
        if (h == ph) {
            int ma = qrow0 + aa;
            #pragma unroll
            for (int j = 0; j < 16; j++) {
                int c = 8 * j + 2 * qq;
                __half2 va = *reinterpret_cast<__half2*>(&o[j][0]);
                __half2 vb = *reinterpret_cast<__half2*>(&o[j][1]);
                stage[(c + 0) * 132 + ma]     = __low2float(va)  * inva;
                stage[(c + 1) * 132 + ma]     = __high2float(va) * inva;
                stage[(c + 0) * 132 + ma + 8] = __low2float(vb)  * invb;
                stage[(c + 1) * 132 + ma + 8] = __high2float(vb) * invb;
            }
        }
        __syncthreads();
        #pragma unroll
        for (int i = 0; i < 8; i++) {
            int idx = tid + i * 512;        // 4096 float4 = 128 ch x 32 x4
            int c = idx >> 5, m4 = (idx & 31) * 4;
            int gc = ph * 128 + c;
            size_t g = (size_t)(b * C + gc) * N + m0 + m4;
            float4 vv = *reinterpret_cast<const float4*>(&stage[c * 132 + m4]);
            float4 xv = *reinterpret_cast<const float4*>(&x[g]);
            vv.x += xv.x; vv.y += xv.y; vv.z += xv.z; vv.w += xv.w;
            *reinterpret_cast<float4*>(&out[g]) = vv;
        }
        __syncthreads();
    }
}

// ----------------------------------------------------------------------------
extern "C" void kernel_launch(void* const* d_in, const int* in_sizes, int n_in,
                              void* d_out, int out_size)
{
    const float* x  = (const float*)d_in[0];
    const float* Wq = (const float*)d_in[1];
    const float* bq = (const float*)d_in[2];
    const float* Wk = (const float*)d_in[3];
    const float* bk = (const float*)d_in[4];
    const float* Wv = (const float*)d_in[5];
    const float* bv = (const float*)d_in[6];
    float* out = (float*)d_out;

    cudaFuncSetAttribute(flash_kernel,
                         cudaFuncAttributeMaxDynamicSharedMemorySize, SMEM_BYTES);
    cudaFuncSetAttribute(flash_kernel,
                         cudaFuncAttributePreferredSharedMemoryCarveout, 100);

    proj_kernel<<<dim3(N / 64, B), 256>>>(x, Wq, bq, Wk, bk, Wv, bv);
    flash_kernel<<<dim3(N / 128, B), 512, SMEM_BYTES>>>(x, out);
}

// round 16
// speedup vs baseline: 1.1543x; 1.1543x over previous
#include <cuda_runtime.h>
#include <cuda.h>
#include <cuda_fp16.h>
#include <math.h>

// ============================================================================
// CrossAttention: B=4, C=256, N=4096, DK=32.
//   K1: QKV projection on f16 tensor cores -> g_q / g_k / g_v f16 scratch.
//   K2: flash attention, 128-query CTAs, 8 warps (32 rows x 128-ch half),
//       K/V tiles fetched by TMA (cp.async.bulk.tensor) + mbarrier double
//       buffer -- removes the LDGSTS 8cyc/op issue floor that bound R9-R15.
//       SW128-swizzled smem, manual XOR in ldmatrix addressing.
// ============================================================================

#define DEV_INLINE __device__ __forceinline__

constexpr int B    = 4;
constexpr int C    = 256;
constexpr int N    = 4096;
constexpr int DK   = 32;
constexpr float SCALE = 0.17677669529663687f;       // 1/sqrt(32)
constexpr float KS = SCALE * 1.4426950408889634f;   // fold into exp2

// f16 scratch (separate tensors, n-major)
__device__ __half g_q[(size_t)B * N * 32];
__device__ __half g_k[(size_t)B * N * 64];    // k in cols [0,32), cols [32,64) pad
__device__ __half g_v[(size_t)B * N * 256];

// ----------------------------------------------------------------------------
// mma / ldmatrix / mbarrier / TMA helpers
// ----------------------------------------------------------------------------
DEV_INLINE void mma_s(float* d, const unsigned* a, unsigned b0, unsigned b1) {
    asm("mma.sync.aligned.m16n8k16.row.col.f32.f16.f16.f32 "
        "{%0,%1,%2,%3}, {%4,%5,%6,%7}, {%8,%9}, {%0,%1,%2,%3};"
        : "+f"(d[0]), "+f"(d[1]), "+f"(d[2]), "+f"(d[3])
        : "r"(a[0]), "r"(a[1]), "r"(a[2]), "r"(a[3]), "r"(b0), "r"(b1));
}

DEV_INLINE void mma_h(unsigned* d, const unsigned* a, unsigned b0, unsigned b1) {
    asm("mma.sync.aligned.m16n8k16.row.col.f16.f16.f16.f16 "
        "{%0,%1}, {%2,%3,%4,%5}, {%6,%7}, {%0,%1};"
        : "+r"(d[0]), "+r"(d[1])
        : "r"(a[0]), "r"(a[1]), "r"(a[2]), "r"(a[3]), "r"(b0), "r"(b1));
}

DEV_INLINE void ldx4(unsigned* r, unsigned saddr) {
    asm volatile("ldmatrix.sync.aligned.m8n8.x4.shared.b16 {%0,%1,%2,%3}, [%4];"
                 : "=r"(r[0]), "=r"(r[1]), "=r"(r[2]), "=r"(r[3]) : "r"(saddr));
}

DEV_INLINE void ldx4t(unsigned* r, unsigned saddr) {
    asm volatile("ldmatrix.sync.aligned.m8n8.x4.trans.shared.b16 {%0,%1,%2,%3}, [%4];"
                 : "=r"(r[0]), "=r"(r[1]), "=r"(r[2]), "=r"(r[3]) : "r"(saddr));
}

DEV_INLINE void mbar_init(unsigned a, unsigned cnt) {
    asm volatile("mbarrier.init.shared.b64 [%0], %1;" :: "r"(a), "r"(cnt) : "memory");
}
DEV_INLINE void mbar_expect(unsigned a, unsigned bytes) {
    asm volatile("mbarrier.arrive.expect_tx.shared.b64 _, [%0], %1;"
                 :: "r"(a), "r"(bytes) : "memory");
}
DEV_INLINE void mbar_wait(unsigned a, unsigned ph) {
    unsigned done;
    asm volatile(
        "{\n\t.reg .pred p;\n\t"
        "mbarrier.try_wait.parity.acquire.cta.shared::cta.b64 p, [%1], %2;\n\t"
        "selp.b32 %0, 1, 0, p;\n\t}"
        : "=r"(done) : "r"(a), "r"(ph) : "memory");
    if (!done) {
        asm volatile(
            "{\n\t.reg .pred P1;\n\t"
            "WL_%=:\n\t"
            "mbarrier.try_wait.parity.acquire.cta.shared::cta.b64 P1, [%0], %1, 0x989680;\n\t"
            "@P1 bra.uni WD_%=;\n\t"
            "bra.uni WL_%=;\n\t"
            "WD_%=:\n\t}"
            :: "r"(a), "r"(ph) : "memory");
    }
}

DEV_INLINE void tma2d(unsigned sdst, const CUtensorMap* map, int c0, int c1,
                      unsigned mbar) {
    asm volatile(
        "cp.async.bulk.tensor.2d.shared::cta.global.tile.mbarrier::complete_tx::bytes "
        "[%0], [%1, {%2, %3}], [%4];"
        :: "r"(sdst), "l"(map), "r"(c0), "r"(c1), "r"(mbar) : "memory");
}

DEV_INLINE float ex2f(float x) {
    float y;
    asm("ex2.approx.ftz.f32 %0, %1;" : "=f"(y) : "f"(x));
    return y;
}
DEV_INLINE unsigned h2ex2(unsigned a) {
    unsigned d;
    asm("ex2.approx.f16x2 %0, %1;" : "=r"(d) : "r"(a));
    return d;
}
DEV_INLINE unsigned pack_h2(float lo, float hi) {
    __half2 h = __floats2half2_rn(lo, hi);
    return *reinterpret_cast<unsigned*>(&h);
}
DEV_INLINE unsigned hmul2u(unsigned a, unsigned s) {
    __half2 r = __hmul2(*reinterpret_cast<__half2*>(&a),
                        *reinterpret_cast<__half2*>(&s));
    return *reinterpret_cast<unsigned*>(&r);
}
DEV_INLINE unsigned hadd2u(unsigned a, unsigned b) {
    __half2 r = __hadd2(*reinterpret_cast<__half2*>(&a),
                        *reinterpret_cast<__half2*>(&b));
    return *reinterpret_cast<unsigned*>(&r);
}
DEV_INLINE unsigned swz(unsigned o) {     // SW128: bits[4:6] ^= bits[7:9]
    return o ^ ((o >> 3) & 0x70);
}

DEV_INLINE float get_bias(int d, const float* bq, const float* bk, const float* bv) {
    return (d < DK) ? bq[d] : (d < 2 * DK) ? bk[d - DK] : bv[d - 2 * DK];
}

// ----------------------------------------------------------------------------
// Kernel 1: projection on tensor cores; epilogue routes to g_q / g_k / g_v.
// ----------------------------------------------------------------------------
__global__ __launch_bounds__(256) void proj_kernel(
    const float* __restrict__ x,
    const float* __restrict__ Wq, const float* __restrict__ bq,
    const float* __restrict__ Wk, const float* __restrict__ bk,
    const float* __restrict__ Wv, const float* __restrict__ bv)
{
    __shared__ __half xs[32][72];
    __shared__ __half ws[320][40];

    const int tid  = threadIdx.x;
    const int lane = tid & 31;
    const int warp = tid >> 5;
    const int wr   = warp & 3;
    const int dh   = (warp >> 2) * 160;
    const int n0   = blockIdx.x * 64;
    const int b    = blockIdx.y;

    const unsigned sx = (unsigned)__cvta_generic_to_shared(xs);
    const unsigned sw = (unsigned)__cvta_generic_to_shared(ws);

    const int lrow  = ((lane >> 3) & 1) * 8 + (lane & 7);
    const int lcol8 = (lane >> 4) * 8;
    const int trow  = ((lane >> 4) & 1) * 8 + (lane & 7);
    const int tcol  = ((lane >> 3) & 1) * 8;

    float acc[20][4];
    #pragma unroll
    for (int j = 0; j < 20; j++)
        #pragma unroll
        for (int i = 0; i < 4; i++) acc[j][i] = 0.f;

    for (int c0 = 0; c0 < C; c0 += 32) {
        #pragma unroll
        for (int rep = 0; rep < 2; rep++) {
            int i  = tid + rep * 256;
            int c  = i >> 4;
            int n4 = (i & 15) * 4;
            float4 v = *reinterpret_cast<const float4*>(
                &x[(size_t)(b * C + c0 + c) * N + n0 + n4]);
            __half2 h0 = __floats2half2_rn(v.x, v.y);
            __half2 h1 = __floats2half2_rn(v.z, v.w);
            uint2 st;
            st.x = *reinterpret_cast<unsigned*>(&h0);
            st.y = *reinterpret_cast<unsigned*>(&h1);
            *reinterpret_cast<uint2*>(&xs[c][n4]) = st;
        }
        #pragma unroll
        for (int rep = 0; rep < 10; rep++) {
            int i  = tid + rep * 256;
            int d  = i >> 3;
            int c4 = (i & 7) * 4;
            const float* src;
            if (d < DK)            src = Wq + (size_t)d * C;
            else if (d < 2 * DK)   src = Wk + (size_t)(d - DK) * C;
            else                   src = Wv + (size_t)(d - 2 * DK) * C;
            float4 v = *reinterpret_cast<const float4*>(&src[c0 + c4]);
            __half2 h0 = __floats2half2_rn(v.x, v.y);
            __half2 h1 = __floats2half2_rn(v.z, v.w);
            uint2 st;
            st.x = *reinterpret_cast<unsigned*>(&h0);
            st.y = *reinterpret_cast<unsigned*>(&h1);
            *reinterpret_cast<uint2*>(&ws[d][c4]) = st;
        }
        __syncthreads();

        #pragma unroll
        for (int kk = 0; kk < 32; kk += 16) {
            unsigned a[4];
            ldx4t(a, sx + ((kk + trow) * 72 + 16 * wr + tcol) * 2);
            #pragma unroll
            for (int j2 = 0; j2 < 10; j2++) {
                unsigned w[4];
                ldx4(w, sw + ((dh + 16 * j2 + lrow) * 40 + kk + lcol8) * 2);
                mma_s(acc[2 * j2],     a, w[0], w[2]);
                mma_s(acc[2 * j2 + 1], a, w[1], w[3]);
            }
        }
        __syncthreads();
    }

    const int r  = lane >> 2;
    const int q2 = 2 * (lane & 3);
    const size_t nA = (size_t)b * N + n0 + 16 * wr + r;
    const size_t nB = nA + 8;
    #pragma unroll
    for (int j = 0; j < 20; j++) {
        int d = dh + 8 * j + q2;
        float b0 = get_bias(d, bq, bk, bv);
        float b1 = get_bias(d + 1, bq, bk, bv);
        __half2 va = __floats2half2_rn(acc[j][0] + b0, acc[j][1] + b1);
        __half2 vb = __floats2half2_rn(acc[j][2] + b0, acc[j][3] + b1);
        if (d < 32) {
            *reinterpret_cast<__half2*>(&g_q[nA * 32 + d]) = va;
            *reinterpret_cast<__half2*>(&g_q[nB * 32 + d]) = vb;
        } else if (d < 64) {
            *reinterpret_cast<__half2*>(&g_k[nA * 64 + d - 32]) = va;
            *reinterpret_cast<__half2*>(&g_k[nB * 64 + d - 32]) = vb;
        } else {
            *reinterpret_cast<__half2*>(&g_v[nA * 256 + d - 64]) = va;
            *reinterpret_cast<__half2*>(&g_v[nB * 256 + d - 64]) = vb;
        }
    }
}

// ----------------------------------------------------------------------------
// Kernel 2: flash attention, 128-query CTAs, 8 warps, TMA K/V pipeline.
// smem: sQ[128][40] (pad, ldmatrix) | sK[2][64 rows x 128B SW128]
//       | sV[2][4 chunks][64 rows x 128B SW128] | mbar[2]
// ----------------------------------------------------------------------------
constexpr int SQ_OFF   = 0;                       // 128*40*2 = 10240
constexpr int SK_OFF   = 10240;                   // 2 x 8192
constexpr int SK_SZ    = 8192;
constexpr int SV_OFF   = SK_OFF + 2 * SK_SZ;      // 26624
constexpr int SV_SZ    = 4 * 8192;                // 32768
constexpr int MB_OFF   = SV_OFF + 2 * SV_SZ;      // 92160
constexpr int SMEM_BYTES = MB_OFF + 16;           // 92176
constexpr unsigned STAGE_BYTES = 8192 + 32768;    // 40960

__global__ __launch_bounds__(256) void flash_kernel(
    const float* __restrict__ x, float* __restrict__ out,
    const __grid_constant__ CUtensorMap tmK,
    const __grid_constant__ CUtensorMap tmV)
{
    extern __shared__ char smem[];
    const unsigned sbase = (unsigned)__cvta_generic_to_shared(smem);

    const int tid  = threadIdx.x;
    const int lane = tid & 31;
    const int warp = tid >> 5;
    const int rgrp = warp & 3;      // 32-row query group
    const int h    = warp >> 2;     // channel half (128 ch)
    const int qrow0 = 32 * rgrp;
    const int b    = blockIdx.y;
    const int m0   = blockIdx.x * 128;
    const int br   = b * N;         // global row base for this batch

    const int lrow  = ((lane >> 3) & 1) * 8 + (lane & 7);
    const int lcol8 = (lane >> 4) * 8;

    // ---- mbarrier init + prologue TMA for stages 0,1 ----
    if (tid == 0) {
        mbar_init(sbase + MB_OFF, 1);
        mbar_init(sbase + MB_OFF + 8, 1);
    }
    __syncthreads();
    if (tid == 0) {
        #pragma unroll
        for (int s = 0; s < 2; s++) {
            unsigned mb = sbase + MB_OFF + 8 * s;
            mbar_expect(mb, STAGE_BYTES);
            tma2d(sbase + SK_OFF + s * SK_SZ, &tmK, 0, br + s * 64, mb);
            #pragma unroll
            for (int cc = 0; cc < 4; cc++)
                tma2d(sbase + SV_OFF + s * SV_SZ + cc * 8192, &tmV,
                      cc * 64, br + s * 64, mb);
        }
    }

    // ---- load Q tile: 128 rows x 32 f16 into padded-40 layout ----
    #pragma unroll
    for (int i = 0; i < 2; i++) {
        int idx = tid + i * 256;
        int m = idx >> 2, part = idx & 3;
        uint4 v = *reinterpret_cast<const uint4*>(
            &g_q[((size_t)br + m0 + m) * 32 + part * 8]);
        *reinterpret_cast<uint4*>(smem + SQ_OFF + (m * 40 + part * 8) * 2) = v;
    }
    __syncthreads();

    // Q fragments: 2 row-tiles x 2 ksteps
    unsigned qf[2][2][4];
    #pragma unroll
    for (int g = 0; g < 2; g++)
        #pragma unroll
        for (int t = 0; t < 2; t++)
            ldx4(qf[g][t],
                 sbase + SQ_OFF + ((qrow0 + 16 * g + lrow) * 40 + 16 * t + lcol8) * 2);

    // O accumulators: 2 row-tiles x 16 ch-tiles x f16x2 pair
    unsigned o[2][16][2];
    #pragma unroll
    for (int g = 0; g < 2; g++)
        #pragma unroll
        for (int j = 0; j < 16; j++) { o[g][j][0] = 0u; o[g][j][1] = 0u; }

    float m2[2][2] = {{-1e30f, -1e30f}, {-1e30f, -1e30f}};
    float L[2][2]  = {{0.f, 0.f}, {0.f, 0.f}};

    for (int kt = 0; kt < 64; kt++) {
        const int buf = kt & 1;

        // wait for this stage's TMA completion
        mbar_wait(sbase + MB_OFF + 8 * buf, (kt >> 1) & 1);

        const unsigned skb = sbase + SK_OFF + buf * SK_SZ;
        const unsigned svb = sbase + SV_OFF + buf * SV_SZ;

        // ---- K fragments once, reused by both row-tiles (SW128 addressing) ----
        unsigned kf[8][4];
        #pragma unroll
        for (int j2 = 0; j2 < 4; j2++) {
            ldx4(kf[2 * j2],     skb + swz((16 * j2 + lrow) * 128 + 0  + lcol8 * 2));
            ldx4(kf[2 * j2 + 1], skb + swz((16 * j2 + lrow) * 128 + 32 + lcol8 * 2));
        }

        unsigned pha[2][8], phb[2][8];

        #pragma unroll
        for (int g = 0; g < 2; g++) {
            // ---- S = Q K^T (f32 accum) ----
            float sacc[8][4];
            #pragma unroll
            for (int j = 0; j < 8; j++)
                #pragma unroll
                for (int i = 0; i < 4; i++) sacc[j][i] = 0.f;

            #pragma unroll
            for (int j2 = 0; j2 < 4; j2++) {
                mma_s(sacc[2 * j2],     qf[g][0], kf[2 * j2][0],     kf[2 * j2][2]);
                mma_s(sacc[2 * j2],     qf[g][1], kf[2 * j2 + 1][0], kf[2 * j2 + 1][2]);
                mma_s(sacc[2 * j2 + 1], qf[g][0], kf[2 * j2][1],     kf[2 * j2][3]);
                mma_s(sacc[2 * j2 + 1], qf[g][1], kf[2 * j2 + 1][1], kf[2 * j2 + 1][3]);
            }

            // ---- online softmax (f32 max, f16x2 exp) ----
            float tma = -1e30f, tmb = -1e30f;
            #pragma unroll
            for (int j = 0; j < 8; j++) {
                tma = fmaxf(tma, fmaxf(sacc[j][0], sacc[j][1]));
                tmb = fmaxf(tmb, fmaxf(sacc[j][2], sacc[j][3]));
            }
            tma = fmaxf(tma, __shfl_xor_sync(0xffffffffu, tma, 1));
            tma = fmaxf(tma, __shfl_xor_sync(0xffffffffu, tma, 2));
            tmb = fmaxf(tmb, __shfl_xor_sync(0xffffffffu, tmb, 1));
            tmb = fmaxf(tmb, __shfl_xor_sync(0xffffffffu, tmb, 2));

            float mna = fmaxf(m2[g][0], KS * tma);
            float mnb = fmaxf(m2[g][1], KS * tmb);
            float alpha_a = ex2f(m2[g][0] - mna);
            float alpha_b = ex2f(m2[g][1] - mnb);
            m2[g][0] = mna; m2[g][1] = mnb;

            unsigned ha2 = pack_h2(alpha_a, alpha_a);
            unsigned hb2 = pack_h2(alpha_b, alpha_b);
            #pragma unroll
            for (int j = 0; j < 16; j++) {
                o[g][j][0] = hmul2u(o[g][j][0], ha2);
                o[g][j][1] = hmul2u(o[g][j][1], hb2);
            }

            #pragma unroll
            for (int j = 0; j < 8; j++) {
                float a0 = fmaf(KS, sacc[j][0], -mna);
                float a1 = fmaf(KS, sacc[j][1], -mna);
                float b0 = fmaf(KS, sacc[j][2], -mnb);
                float b1 = fmaf(KS, sacc[j][3], -mnb);
                pha[g][j] = h2ex2(pack_h2(a0, a1));
                phb[g][j] = h2ex2(pack_h2(b0, b1));
            }

            unsigned saA = hadd2u(hadd2u(hadd2u(pha[g][0], pha[g][1]),
                                         hadd2u(pha[g][2], pha[g][3])),
                                  hadd2u(hadd2u(pha[g][4], pha[g][5]),
                                         hadd2u(pha[g][6], pha[g][7])));
            unsigned sbB = hadd2u(hadd2u(hadd2u(phb[g][0], phb[g][1]),
                                         hadd2u(phb[g][2], phb[g][3])),
                                  hadd2u(hadd2u(phb[g][4], phb[g][5]),
                                         hadd2u(phb[g][6], phb[g][7])));
            __half2 hva = *reinterpret_cast<__half2*>(&saA);
            __half2 hvb = *reinterpret_cast<__half2*>(&sbB);
            float la = __low2float(hva) + __high2float(hva);
            float lb = __low2float(hvb) + __high2float(hvb);
            la += __shfl_xor_sync(0xffffffffu, la, 1);
            la += __shfl_xor_sync(0xffffffffu, la, 2);
            lb += __shfl_xor_sync(0xffffffffu, lb, 1);
            lb += __shfl_xor_sync(0xffffffffu, lb, 2);
            L[g][0] = L[g][0] * alpha_a + la;
            L[g][1] = L[g][1] * alpha_b + lb;
        }

        // ---- O += P V : each V fragment feeds BOTH row-tiles ----
        #pragma unroll
        for (int t = 0; t < 4; t++) {
            unsigned pa0[4] = {pha[0][2 * t], phb[0][2 * t],
                               pha[0][2 * t + 1], phb[0][2 * t + 1]};
            unsigned pa1[4] = {pha[1][2 * t], phb[1][2 * t],
                               pha[1][2 * t + 1], phb[1][2 * t + 1]};
            #pragma unroll
            for (int u = 0; u < 8; u++) {
                int ch = h * 128 + 16 * u + lcol8;
                unsigned vf[4];
                ldx4t(vf, svb + (ch >> 6) * 8192
                          + swz((16 * t + lrow) * 128 + (ch & 63) * 2));
                mma_h(o[0][2 * u],     pa0, vf[0], vf[1]);
                mma_h(o[0][2 * u + 1], pa0, vf[2], vf[3]);
                mma_h(o[1][2 * u],     pa1, vf[0], vf[1]);
                mma_h(o[1][2 * u + 1], pa1, vf[2], vf[3]);
            }
        }
        __syncthreads();   // all warps done with this buffer

        // refill this buffer with stage kt+2
        if (tid == 0 && kt + 2 < 64) {
            int s = kt + 2;
            unsigned mb = sbase + MB_OFF + 8 * buf;
            mbar_expect(mb, STAGE_BYTES);
            tma2d(sbase + SK_OFF + buf * SK_SZ, &tmK, 0, br + s * 64, mb);
            #pragma unroll
            for (int cc = 0; cc < 4; cc++)
                tma2d(sbase + SV_OFF + buf * SV_SZ + cc * 8192, &tmV,
                      cc * 64, br + s * 64, mb);
        }
    }

    // ---- epilogue: normalize, transpose via smem, residual add ----
    const int qq = lane & 3;
    const int aa = lane >> 2;

    __syncthreads();
    float* stage = reinterpret_cast<float*>(smem);   // [128 ch][132 m] fp32
    #pragma unroll
    for (int ph = 0; ph < 2; ph++) {
        if (h == ph) {
            #pragma unroll
            for (int g = 0; g < 2; g++) {
                float inva = 1.f / L[g][0];
                float invb = 1.f / L[g][1];
                int ma = qrow0 + 16 * g + aa;
                #pragma unroll
                for (int j = 0; j < 16; j++) {
                    int c = 8 * j + 2 * qq;
                    __half2 va = *reinterpret_cast<__half2*>(&o[g][j][0]);
                    __half2 vb = *reinterpret_cast<__half2*>(&o[g][j][1]);
                    stage[(c + 0) * 132 + ma]     = __low2float(va)  * inva;
                    stage[(c + 1) * 132 + ma]     = __high2float(va) * inva;
                    stage[(c + 0) * 132 + ma + 8] = __low2float(vb)  * invb;
                    stage[(c + 1) * 132 + ma + 8] = __high2float(vb) * invb;
                }
            }
        }
        __syncthreads();
        #pragma unroll
        for (int i = 0; i < 16; i++) {
            int idx = tid + i * 256;        // 4096 float4 = 128 ch x 32
            int c = idx >> 5, m4 = (idx & 31) * 4;
            int gc = ph * 128 + c;
            size_t gg = (size_t)(b * C + gc) * N + m0 + m4;
            float4 vv = *reinterpret_cast<const float4*>(&stage[c * 132 + m4]);
            float4 xv = *reinterpret_cast<const float4*>(&x[gg]);
            vv.x += xv.x; vv.y += xv.y; vv.z += xv.z; vv.w += xv.w;
            *reinterpret_cast<float4*>(&out[gg]) = vv;
        }
        __syncthreads();
    }
}

// ----------------------------------------------------------------------------
// Host: build tensor maps via driver entry point (no -lcuda needed).
// ----------------------------------------------------------------------------
typedef CUresult (*EncodeTiledFn)(
    CUtensorMap*, CUtensorMapDataType, cuuint32_t, void*,
    const cuuint64_t*, const cuuint64_t*, const cuuint32_t*, const cuuint32_t*,
    CUtensorMapInterleave, CUtensorMapSwizzle, CUtensorMapL2promotion,
    CUtensorMapFloatOOBfill);

static void make_map_2d(EncodeTiledFn enc, CUtensorMap* m, void* base,
                        unsigned dim0, unsigned rows, unsigned stride_bytes,
                        unsigned box0, unsigned box1)
{
    cuuint64_t gd[2] = {dim0, rows};
    cuuint64_t gs[1] = {stride_bytes};
    cuuint32_t bx[2] = {box0, box1};
    cuuint32_t es[2] = {1, 1};
    enc(m, CU_TENSOR_MAP_DATA_TYPE_UINT16, 2, base, gd, gs, bx, es,
        CU_TENSOR_MAP_INTERLEAVE_NONE, CU_TENSOR_MAP_SWIZZLE_128B,
        CU_TENSOR_MAP_L2_PROMOTION_L2_128B, CU_TENSOR_MAP_FLOAT_OOB_FILL_NONE);
}

extern "C" void kernel_launch(void* const* d_in, const int* in_sizes, int n_in,
                              void* d_out, int out_size)
{
    const float* x  = (const float*)d_in[0];
    const float* Wq = (const float*)d_in[1];
    const float* bq = (const float*)d_in[2];
    const float* Wk = (const float*)d_in[3];
    const float* bk = (const float*)d_in[4];
    const float* Wv = (const float*)d_in[5];
    const float* bv = (const float*)d_in[6];
    float* out = (float*)d_out;

    // driver entry point for cuTensorMapEncodeTiled
    EncodeTiledFn enc = nullptr;
    {
        void* fp = nullptr;
        cudaDriverEntryPointQueryResult st;
        cudaGetDriverEntryPointByVersion("cuTensorMapEncodeTiled", &fp, 12000,
                                         cudaEnableDefault, &st);
        enc = (EncodeTiledFn)fp;
    }

    void *pk = nullptr, *pv = nullptr;
    cudaGetSymbolAddress(&pk, g_k);
    cudaGetSymbolAddress(&pv, g_v);

    CUtensorMap tmK, tmV;
    make_map_2d(enc, &tmK, pk, 64,  B * N, 64 * 2,  64, 64);
    make_map_2d(enc, &tmV, pv, 256, B * N, 256 * 2, 64, 64);

    cudaFuncSetAttribute(flash_kernel,
                         cudaFuncAttributeMaxDynamicSharedMemorySize, SMEM_BYTES);
    cudaFuncSetAttribute(flash_kernel,
                         cudaFuncAttributePreferredSharedMemoryCarveout, 100);

    proj_kernel<<<dim3(N / 64, B), 256>>>(x, Wq, bq, Wk, bk, Wv, bv);
    flash_kernel<<<dim3(N / 128, B), 256, SMEM_BYTES>>>(x, out, tmK, tmV);
}

// round 17
// speedup vs baseline: 1.1636x; 1.0081x over previous
#include <cuda_runtime.h>
#include <cuda.h>
#include <cuda_fp16.h>
#include <math.h>

// ============================================================================
// CrossAttention: B=4, C=256, N=4096, DK=32.
//   K1: QKV projection on f16 tensor cores -> g_q / g_k / g_v f16 scratch.
//   K2: flash attention, 128-query CTAs, 512 threads / 16 warps
//       (warp = 16 rows x 128-ch half; 4 warps/SMSP hides the softmax chain),
//       K/V via TMA + mbarrier double buffer (no LDGSTS issue floor),
//       SW128 smem with manual XOR addressing, f16x2 exp, f16-D PV mma.
// ============================================================================

#define DEV_INLINE __device__ __forceinline__

constexpr int B    = 4;
constexpr int C    = 256;
constexpr int N    = 4096;
constexpr int DK   = 32;
constexpr float SCALE = 0.17677669529663687f;       // 1/sqrt(32)
constexpr float KS = SCALE * 1.4426950408889634f;   // fold into exp2

// f16 scratch (separate tensors, n-major)
__device__ __half g_q[(size_t)B * N * 32];
__device__ __half g_k[(size_t)B * N * 64];    // k in cols [0,32), cols [32,64) pad
__device__ __half g_v[(size_t)B * N * 256];

// ----------------------------------------------------------------------------
// mma / ldmatrix / mbarrier / TMA helpers
// ----------------------------------------------------------------------------
DEV_INLINE void mma_s(float* d, const unsigned* a, unsigned b0, unsigned b1) {
    asm("mma.sync.aligned.m16n8k16.row.col.f32.f16.f16.f32 "
        "{%0,%1,%2,%3}, {%4,%5,%6,%7}, {%8,%9}, {%0,%1,%2,%3};"
        : "+f"(d[0]), "+f"(d[1]), "+f"(d[2]), "+f"(d[3])
        : "r"(a[0]), "r"(a[1]), "r"(a[2]), "r"(a[3]), "r"(b0), "r"(b1));
}

DEV_INLINE void mma_h(unsigned* d, const unsigned* a, unsigned b0, unsigned b1) {
    asm("mma.sync.aligned.m16n8k16.row.col.f16.f16.f16.f16 "
        "{%0,%1}, {%2,%3,%4,%5}, {%6,%7}, {%0,%1};"
        : "+r"(d[0]), "+r"(d[1])
        : "r"(a[0]), "r"(a[1]), "r"(a[2]), "r"(a[3]), "r"(b0), "r"(b1));
}

DEV_INLINE void ldx4(unsigned* r, unsigned saddr) {
    asm volatile("ldmatrix.sync.aligned.m8n8.x4.shared.b16 {%0,%1,%2,%3}, [%4];"
                 : "=r"(r[0]), "=r"(r[1]), "=r"(r[2]), "=r"(r[3]) : "r"(saddr));
}

DEV_INLINE void ldx4t(unsigned* r, unsigned saddr) {
    asm volatile("ldmatrix.sync.aligned.m8n8.x4.trans.shared.b16 {%0,%1,%2,%3}, [%4];"
                 : "=r"(r[0]), "=r"(r[1]), "=r"(r[2]), "=r"(r[3]) : "r"(saddr));
}

DEV_INLINE void mbar_init(unsigned a, unsigned cnt) {
    asm volatile("mbarrier.init.shared.b64 [%0], %1;" :: "r"(a), "r"(cnt) : "memory");
}
DEV_INLINE void mbar_expect(unsigned a, unsigned bytes) {
    asm volatile("mbarrier.arrive.expect_tx.shared.b64 _, [%0], %1;"
                 :: "r"(a), "r"(bytes) : "memory");
}
DEV_INLINE void mbar_wait(unsigned a, unsigned ph) {
    unsigned done;
    asm volatile(
        "{\n\t.reg .pred p;\n\t"
        "mbarrier.try_wait.parity.acquire.cta.shared::cta.b64 p, [%1], %2;\n\t"
        "selp.b32 %0, 1, 0, p;\n\t}"
        : "=r"(done) : "r"(a), "r"(ph) : "memory");
    if (!done) {
        asm volatile(
            "{\n\t.reg .pred P1;\n\t"
            "WL_%=:\n\t"
            "mbarrier.try_wait.parity.acquire.cta.shared::cta.b64 P1, [%0], %1, 0x989680;\n\t"
            "@P1 bra.uni WD_%=;\n\t"
            "bra.uni WL_%=;\n\t"
            "WD_%=:\n\t}"
            :: "r"(a), "r"(ph) : "memory");
    }
}

DEV_INLINE void tma2d(unsigned sdst, const CUtensorMap* map, int c0, int c1,
                      unsigned mbar) {
    asm volatile(
        "cp.async.bulk.tensor.2d.shared::cta.global.tile.mbarrier::complete_tx::bytes "
        "[%0], [%1, {%2, %3}], [%4];"
        :: "r"(sdst), "l"(map), "r"(c0), "r"(c1), "r"(mbar) : "memory");
}

DEV_INLINE float ex2f(float x) {
    float y;
    asm("ex2.approx.ftz.f32 %0, %1;" : "=f"(y) : "f"(x));
    return y;
}
DEV_INLINE unsigned h2ex2(unsigned a) {
    unsigned d;
    asm("ex2.approx.f16x2 %0, %1;" : "=r"(d) : "r"(a));
    return d;
}
DEV_INLINE unsigned pack_h2(float lo, float hi) {
    __half2 h = __floats2half2_rn(lo, hi);
    return *reinterpret_cast<unsigned*>(&h);
}
DEV_INLINE unsigned hmul2u(unsigned a, unsigned s) {
    __half2 r = __hmul2(*reinterpret_cast<__half2*>(&a),
                        *reinterpret_cast<__half2*>(&s));
    return *reinterpret_cast<unsigned*>(&r);
}
DEV_INLINE unsigned hadd2u(unsigned a, unsigned b) {
    __half2 r = __hadd2(*reinterpret_cast<__half2*>(&a),
                        *reinterpret_cast<__half2*>(&b));
    return *reinterpret_cast<unsigned*>(&r);
}
DEV_INLINE unsigned swz(unsigned o) {     // SW128: bits[4:6] ^= bits[7:9]
    return o ^ ((o >> 3) & 0x70);
}

DEV_INLINE float get_bias(int d, const float* bq, const float* bk, const float* bv) {
    return (d < DK) ? bq[d] : (d < 2 * DK) ? bk[d - DK] : bv[d - 2 * DK];
}

// ----------------------------------------------------------------------------
// Kernel 1: projection on tensor cores; epilogue routes to g_q / g_k / g_v.
// ----------------------------------------------------------------------------
__global__ __launch_bounds__(256) void proj_kernel(
    const float* __restrict__ x,
    const float* __restrict__ Wq, const float* __restrict__ bq,
    const float* __restrict__ Wk, const float* __restrict__ bk,
    const float* __restrict__ Wv, const float* __restrict__ bv)
{
    __shared__ __half xs[32][72];
    __shared__ __half ws[320][40];

    const int tid  = threadIdx.x;
    const int lane = tid & 31;
    const int warp = tid >> 5;
    const int wr   = warp & 3;
    const int dh   = (warp >> 2) * 160;
    const int n0   = blockIdx.x * 64;
    const int b    = blockIdx.y;

    const unsigned sx = (unsigned)__cvta_generic_to_shared(xs);
    const unsigned sw = (unsigned)__cvta_generic_to_shared(ws);

    const int lrow  = ((lane >> 3) & 1) * 8 + (lane & 7);
    const int lcol8 = (lane >> 4) * 8;
    const int trow  = ((lane >> 4) & 1) * 8 + (lane & 7);
    const int tcol  = ((lane >> 3) & 1) * 8;

    float acc[20][4];
    #pragma unroll
    for (int j = 0; j < 20; j++)
        #pragma unroll
        for (int i = 0; i < 4; i++) acc[j][i] = 0.f;

    for (int c0 = 0; c0 < C; c0 += 32) {
        #pragma unroll
        for (int rep = 0; rep < 2; rep++) {
            int i  = tid + rep * 256;
            int c  = i >> 4;
            int n4 = (i & 15) * 4;
            float4 v = *reinterpret_cast<const float4*>(
                &x[(size_t)(b * C + c0 + c) * N + n0 + n4]);
            __half2 h0 = __floats2half2_rn(v.x, v.y);
            __half2 h1 = __floats2half2_rn(v.z, v.w);
            uint2 st;
            st.x = *reinterpret_cast<unsigned*>(&h0);
            st.y = *reinterpret_cast<unsigned*>(&h1);
            *reinterpret_cast<uint2*>(&xs[c][n4]) = st;
        }
        #pragma unroll
        for (int rep = 0; rep < 10; rep++) {
            int i  = tid + rep * 256;
            int d  = i >> 3;
            int c4 = (i & 7) * 4;
            const float* src;
            if (d < DK)            src = Wq + (size_t)d * C;
            else if (d < 2 * DK)   src = Wk + (size_t)(d - DK) * C;
            else                   src = Wv + (size_t)(d - 2 * DK) * C;
            float4 v = *reinterpret_cast<const float4*>(&src[c0 + c4]);
            __half2 h0 = __floats2half2_rn(v.x, v.y);
            __half2 h1 = __floats2half2_rn(v.z, v.w);
            uint2 st;
            st.x = *reinterpret_cast<unsigned*>(&h0);
            st.y = *reinterpret_cast<unsigned*>(&h1);
            *reinterpret_cast<uint2*>(&ws[d][c4]) = st;
        }
        __syncthreads();

        #pragma unroll
        for (int kk = 0; kk < 32; kk += 16) {
            unsigned a[4];
            ldx4t(a, sx + ((kk + trow) * 72 + 16 * wr + tcol) * 2);
            #pragma unroll
            for (int j2 = 0; j2 < 10; j2++) {
                unsigned w[4];
                ldx4(w, sw + ((dh + 16 * j2 + lrow) * 40 + kk + lcol8) * 2);
                mma_s(acc[2 * j2],     a, w[0], w[2]);
                mma_s(acc[2 * j2 + 1], a, w[1], w[3]);
            }
        }
        __syncthreads();
    }

    const int r  = lane >> 2;
    const int q2 = 2 * (lane & 3);
    const size_t nA = (size_t)b * N + n0 + 16 * wr + r;
    const size_t nB = nA + 8;
    #pragma unroll
    for (int j = 0; j < 20; j++) {
        int d = dh + 8 * j + q2;
        float b0 = get_bias(d, bq, bk, bv);
        float b1 = get_bias(d + 1, bq, bk, bv);
        __half2 va = __floats2half2_rn(acc[j][0] + b0, acc[j][1] + b1);
        __half2 vb = __floats2half2_rn(acc[j][2] + b0, acc[j][3] + b1);
        if (d < 32) {
            *reinterpret_cast<__half2*>(&g_q[nA * 32 + d]) = va;
            *reinterpret_cast<__half2*>(&g_q[nB * 32 + d]) = vb;
        } else if (d < 64) {
            *reinterpret_cast<__half2*>(&g_k[nA * 64 + d - 32]) = va;
            *reinterpret_cast<__half2*>(&g_k[nB * 64 + d - 32]) = vb;
        } else {
            *reinterpret_cast<__half2*>(&g_v[nA * 256 + d - 64]) = va;
            *reinterpret_cast<__half2*>(&g_v[nB * 256 + d - 64]) = vb;
        }
    }
}

// ----------------------------------------------------------------------------
// Kernel 2: flash attention, 128-query CTAs, 512 threads / 16 warps, TMA K/V.
//   warp w: rgrp = w&7 (16-row block), h = w>>3 (128-ch half).
// smem: sQ[128][40] | sK[2][64 x 128B SW128] | sV[2][4][64 x 128B SW128] | mbar
// ----------------------------------------------------------------------------
constexpr int SQ_OFF   = 0;                       // 128*40*2 = 10240
constexpr int SK_OFF   = 10240;                   // 2 x 8192
constexpr int SK_SZ    = 8192;
constexpr int SV_OFF   = SK_OFF + 2 * SK_SZ;      // 26624
constexpr int SV_SZ    = 4 * 8192;                // 32768
constexpr int MB_OFF   = SV_OFF + 2 * SV_SZ;      // 92160
constexpr int SMEM_BYTES = MB_OFF + 16;           // 92176
constexpr unsigned STAGE_BYTES = 8192 + 32768;    // 40960

__global__ __launch_bounds__(512) void flash_kernel(
    const float* __restrict__ x, float* __restrict__ out,
    const __grid_constant__ CUtensorMap tmK,
    const __grid_constant__ CUtensorMap tmV)
{
    extern __shared__ char smem[];
    const unsigned sbase = (unsigned)__cvta_generic_to_shared(smem);

    const int tid  = threadIdx.x;
    const int lane = tid & 31;
    const int warp = tid >> 5;
    const int rgrp = warp & 7;      // 16-row query group
    const int h    = warp >> 3;     // channel half (128 ch)
    const int qrow0 = 16 * rgrp;
    const int b    = blockIdx.y;
    const int m0   = blockIdx.x * 128;
    const int br   = b * N;         // global row base for this batch

    const int lrow  = ((lane >> 3) & 1) * 8 + (lane & 7);
    const int lcol8 = (lane >> 4) * 8;

    // ---- mbarrier init + prologue TMA for stages 0,1 ----
    if (tid == 0) {
        mbar_init(sbase + MB_OFF, 1);
        mbar_init(sbase + MB_OFF + 8, 1);
    }
    __syncthreads();
    if (tid == 0) {
        #pragma unroll
        for (int s = 0; s < 2; s++) {
            unsigned mb = sbase + MB_OFF + 8 * s;
            mbar_expect(mb, STAGE_BYTES);
            tma2d(sbase + SK_OFF + s * SK_SZ, &tmK, 0, br + s * 64, mb);
            #pragma unroll
            for (int cc = 0; cc < 4; cc++)
                tma2d(sbase + SV_OFF + s * SV_SZ + cc * 8192, &tmV,
                      cc * 64, br + s * 64, mb);
        }
    }

    // ---- load Q tile: 128 rows x 32 f16 into padded-40 layout ----
    {
        int m = tid >> 2, part = tid & 3;
        uint4 v = *reinterpret_cast<const uint4*>(
            &g_q[((size_t)br + m0 + m) * 32 + part * 8]);
        *reinterpret_cast<uint4*>(smem + SQ_OFF + (m * 40 + part * 8) * 2) = v;
    }
    __syncthreads();

    // Q fragments: 2 ksteps
    unsigned qf[2][4];
    #pragma unroll
    for (int t = 0; t < 2; t++)
        ldx4(qf[t], sbase + SQ_OFF + ((qrow0 + lrow) * 40 + 16 * t + lcol8) * 2);

    // O accumulators: 16 ch-tiles x f16x2 pair = 32 regs
    unsigned o[16][2];
    #pragma unroll
    for (int j = 0; j < 16; j++) { o[j][0] = 0u; o[j][1] = 0u; }

    float m2a = -1e30f, m2b = -1e30f;
    float La = 0.f, Lb = 0.f;

    for (int kt = 0; kt < 64; kt++) {
        const int buf = kt & 1;

        // wait for this stage's TMA completion
        mbar_wait(sbase + MB_OFF + 8 * buf, (kt >> 1) & 1);

        const unsigned skb = sbase + SK_OFF + buf * SK_SZ;
        const unsigned svb = sbase + SV_OFF + buf * SV_SZ;

        // ---- S = Q K^T (f32 accum): 8 n-tiles x 2 ksteps ----
        float sacc[8][4];
        #pragma unroll
        for (int j = 0; j < 8; j++)
            #pragma unroll
            for (int i = 0; i < 4; i++) sacc[j][i] = 0.f;

        #pragma unroll
        for (int j2 = 0; j2 < 4; j2++) {
            unsigned k0[4], k1[4];
            ldx4(k0, skb + swz((16 * j2 + lrow) * 128 + 0  + lcol8 * 2));
            ldx4(k1, skb + swz((16 * j2 + lrow) * 128 + 32 + lcol8 * 2));
            mma_s(sacc[2 * j2],     qf[0], k0[0], k0[2]);
            mma_s(sacc[2 * j2],     qf[1], k1[0], k1[2]);
            mma_s(sacc[2 * j2 + 1], qf[0], k0[1], k0[3]);
            mma_s(sacc[2 * j2 + 1], qf[1], k1[1], k1[3]);
        }

        // ---- online softmax (f32 max, f16x2 exp) ----
        float tma = -1e30f, tmb = -1e30f;
        #pragma unroll
        for (int j = 0; j < 8; j++) {
            tma = fmaxf(tma, fmaxf(sacc[j][0], sacc[j][1]));
            tmb = fmaxf(tmb, fmaxf(sacc[j][2], sacc[j][3]));
        }
        tma = fmaxf(tma, __shfl_xor_sync(0xffffffffu, tma, 1));
        tma = fmaxf(tma, __shfl_xor_sync(0xffffffffu, tma, 2));
        tmb = fmaxf(tmb, __shfl_xor_sync(0xffffffffu, tmb, 1));
        tmb = fmaxf(tmb, __shfl_xor_sync(0xffffffffu, tmb, 2));

        float mna = fmaxf(m2a, KS * tma);
        float mnb = fmaxf(m2b, KS * tmb);
        float alpha_a = ex2f(m2a - mna);
        float alpha_b = ex2f(m2b - mnb);
        m2a = mna; m2b = mnb;

        unsigned ha2 = pack_h2(alpha_a, alpha_a);
        unsigned hb2 = pack_h2(alpha_b, alpha_b);
        #pragma unroll
        for (int j = 0; j < 16; j++) {
            o[j][0] = hmul2u(o[j][0], ha2);
            o[j][1] = hmul2u(o[j][1], hb2);
        }

        // p = ex2(KS*s - m) as f16x2; result IS the PV A-fragment
        unsigned pha[8], phb[8];
        #pragma unroll
        for (int j = 0; j < 8; j++) {
            float a0 = fmaf(KS, sacc[j][0], -mna);
            float a1 = fmaf(KS, sacc[j][1], -mna);
            float b0 = fmaf(KS, sacc[j][2], -mnb);
            float b1 = fmaf(KS, sacc[j][3], -mnb);
            pha[j] = h2ex2(pack_h2(a0, a1));
            phb[j] = h2ex2(pack_h2(b0, b1));
        }

        // row-sum via half2 tree, f32 finish
        unsigned saA = hadd2u(hadd2u(hadd2u(pha[0], pha[1]), hadd2u(pha[2], pha[3])),
                              hadd2u(hadd2u(pha[4], pha[5]), hadd2u(pha[6], pha[7])));
        unsigned sbB = hadd2u(hadd2u(hadd2u(phb[0], phb[1]), hadd2u(phb[2], phb[3])),
                              hadd2u(hadd2u(phb[4], phb[5]), hadd2u(phb[6], phb[7])));
        __half2 hva = *reinterpret_cast<__half2*>(&saA);
        __half2 hvb = *reinterpret_cast<__half2*>(&sbB);
        float la = __low2float(hva) + __high2float(hva);
        float lb = __low2float(hvb) + __high2float(hvb);
        la += __shfl_xor_sync(0xffffffffu, la, 1);
        la += __shfl_xor_sync(0xffffffffu, la, 2);
        lb += __shfl_xor_sync(0xffffffffu, lb, 1);
        lb += __shfl_xor_sync(0xffffffffu, lb, 2);
        La = La * alpha_a + la;
        Lb = Lb * alpha_b + lb;

        // ---- O += P V : 4 ksteps x 16 ch-tiles ----
        #pragma unroll
        for (int t = 0; t < 4; t++) {
            unsigned pa[4] = {pha[2 * t], phb[2 * t], pha[2 * t + 1], phb[2 * t + 1]};
            #pragma unroll
            for (int u = 0; u < 8; u++) {
                int ch = h * 128 + 16 * u + lcol8;
                unsigned vf[4];
                ldx4t(vf, svb + (ch >> 6) * 8192
                          + swz((16 * t + lrow) * 128 + (ch & 63) * 2));
                mma_h(o[2 * u],     pa, vf[0], vf[1]);
                mma_h(o[2 * u + 1], pa, vf[2], vf[3]);
            }
        }
        __syncthreads();   // all warps done with this buffer

        // refill this buffer with stage kt+2
        if (tid == 0 && kt + 2 < 64) {
            int s = kt + 2;
            unsigned mb = sbase + MB_OFF + 8 * buf;
            mbar_expect(mb, STAGE_BYTES);
            tma2d(sbase + SK_OFF + buf * SK_SZ, &tmK, 0, br + s * 64, mb);
            #pragma unroll
            for (int cc = 0; cc < 4; cc++)
                tma2d(sbase + SV_OFF + buf * SV_SZ + cc * 8192, &tmV,
                      cc * 64, br + s * 64, mb);
        }
    }

    // ---- epilogue: normalize, transpose via smem, residual add ----
    const float inva = 1.f / La;
    const float invb = 1.f / Lb;
    const int qq = lane & 3;
    const int aa = lane >> 2;

    __syncthreads();
    float* stage = reinterpret_cast<float*>(smem);   // [128 ch][132 m] fp32
    #pragma unroll
    for (int ph = 0; ph < 2; ph++) {
        if (h == ph) {
            int ma = qrow0 + aa;
            #pragma unroll
            for (int j = 0; j < 16; j++) {
                int c = 8 * j + 2 * qq;
                __half2 va = *reinterpret_cast<__half2*>(&o[j][0]);
                __half2 vb = *reinterpret_cast<__half2*>(&o[j][1]);
                stage[(c + 0) * 132 + ma]     = __low2float(va)  * inva;
                stage[(c + 1) * 132 + ma]     = __high2float(va) * inva;
                stage[(c + 0) * 132 + ma + 8] = __low2float(vb)  * invb;
                stage[(c + 1) * 132 + ma + 8] = __high2float(vb) * invb;
            }
        }
        __syncthreads();
        #pragma unroll
        for (int i = 0; i < 8; i++) {
            int idx = tid + i * 512;        // 4096 float4 = 128 ch x 32
            int c = idx >> 5, m4 = (idx & 31) * 4;
            int gc = ph * 128 + c;
            size_t gg = (size_t)(b * C + gc) * N + m0 + m4;
            float4 vv = *reinterpret_cast<const float4*>(&stage[c * 132 + m4]);
            float4 xv = *reinterpret_cast<const float4*>(&x[gg]);
            vv.x += xv.x; vv.y += xv.y; vv.z += xv.z; vv.w += xv.w;
            *reinterpret_cast<float4*>(&out[gg]) = vv;
        }
        __syncthreads();
    }
}

// ----------------------------------------------------------------------------
// Host: build tensor maps via driver entry point.
// ----------------------------------------------------------------------------
typedef CUresult (*EncodeTiledFn)(
    CUtensorMap*, CUtensorMapDataType, cuuint32_t, void*,
    const cuuint64_t*, const cuuint64_t*, const cuuint32_t*, const cuuint32_t*,
    CUtensorMapInterleave, CUtensorMapSwizzle, CUtensorMapL2promotion,
    CUtensorMapFloatOOBfill);

static void make_map_2d(EncodeTiledFn enc, CUtensorMap* m, void* base,
                        unsigned dim0, unsigned rows, unsigned stride_bytes,
                        unsigned box0, unsigned box1)
{
    cuuint64_t gd[2] = {dim0, rows};
    cuuint64_t gs[1] = {stride_bytes};
    cuuint32_t bx[2] = {box0, box1};
    cuuint32_t es[2] = {1, 1};
    enc(m, CU_TENSOR_MAP_DATA_TYPE_UINT16, 2, base, gd, gs, bx, es,
        CU_TENSOR_MAP_INTERLEAVE_NONE, CU_TENSOR_MAP_SWIZZLE_128B,
        CU_TENSOR_MAP_L2_PROMOTION_L2_128B, CU_TENSOR_MAP_FLOAT_OOB_FILL_NONE);
}

extern "C" void kernel_launch(void* const* d_in, const int* in_sizes, int n_in,
                              void* d_out, int out_size)
{
    const float* x  = (const float*)d_in[0];
    const float* Wq = (const float*)d_in[1];
    const float* bq = (const float*)d_in[2];
    const float* Wk = (const float*)d_in[3];
    const float* bk = (const float*)d_in[4];
    const float* Wv = (const float*)d_in[5];
    const float* bv = (const float*)d_in[6];
    float* out = (float*)d_out;

    EncodeTiledFn enc = nullptr;
    {
        void* fp = nullptr;
        cudaDriverEntryPointQueryResult st;
        cudaGetDriverEntryPointByVersion("cuTensorMapEncodeTiled", &fp, 12000,
                                         cudaEnableDefault, &st);
        enc = (EncodeTiledFn)fp;
    }

    void *pk = nullptr, *pv = nullptr;
    cudaGetSymbolAddress(&pk, g_k);
    cudaGetSymbolAddress(&pv, g_v);

    CUtensorMap tmK, tmV;
    make_map_2d(enc, &tmK, pk, 64,  B * N, 64 * 2,  64, 64);
    make_map_2d(enc, &tmV, pv, 256, B * N, 256 * 2, 64, 64);

    cudaFuncSetAttribute(flash_kernel,
                         cudaFuncAttributeMaxDynamicSharedMemorySize, SMEM_BYTES);
    cudaFuncSetAttribute(flash_kernel,
                         cudaFuncAttributePreferredSharedMemoryCarveout, 100);

    proj_kernel<<<dim3(N / 64, B), 256>>>(x, Wq, bq, Wk, bk, Wv, bv);
    flash_kernel<<<dim3(N / 128, B), 512, SMEM_BYTES>>>(x, out, tmK, tmV);
}